// round 7
// baseline (speedup 1.0000x reference)
#include <cuda_runtime.h>
#include <math.h>

namespace {

constexpr int kB     = 4;      // basis kernels
constexpr int kH     = 8;      // heads
constexpr int kNI    = 16384;  // BATCH * N
constexpr int kBlk   = 64;     // threads per CTA
constexpr int kCPT   = 2;      // columns per thread (f32x2 across columns)
constexpr int kCols  = kBlk * kCPT;   // 128 columns per CTA
constexpr int kHPT   = 2;      // heads per CTA
constexpr int kTT    = 8;      // timesteps per spike chunk
constexpr int kNBuf  = 6;      // spike buffers (40-timestep lookahead)
constexpr int kSpkRowB   = kCols * 4;        // 512 B
constexpr int kSpkChunkB = kTT * kSpkRowB;   // 4096 B

__device__ int g_dt_default = 1;

__device__ __forceinline__ unsigned long long pack2(float lo, float hi) {
    unsigned long long r;
    asm("mov.b64 %0, {%1, %2};" : "=l"(r) : "f"(lo), "f"(hi));
    return r;
}
__device__ __forceinline__ void unpack2(unsigned long long v, float& lo, float& hi) {
    asm("mov.b64 {%0, %1}, %2;" : "=f"(lo), "=f"(hi) : "l"(v));
}
__device__ __forceinline__ unsigned long long fma2(unsigned long long a,
                                                   unsigned long long b,
                                                   unsigned long long c) {
    unsigned long long r;
    asm("fma.rn.f32x2 %0, %1, %2, %3;" : "=l"(r) : "l"(a), "l"(b), "l"(c));
    return r;
}
__device__ __forceinline__ unsigned long long mul2(unsigned long long a,
                                                   unsigned long long b) {
    unsigned long long r;
    asm("mul.rn.f32x2 %0, %1, %2;" : "=l"(r) : "l"(a), "l"(b));
    return r;
}

__device__ __forceinline__ unsigned smem_u32(const void* p) {
    unsigned r;
    asm("{ .reg .u64 t; cvta.to.shared.u64 t, %1; cvt.u32.u64 %0, t; }"
        : "=r"(r) : "l"(p));
    return r;
}
__device__ __forceinline__ void mbar_init(unsigned addr, unsigned count) {
    asm volatile("mbarrier.init.shared.b64 [%0], %1;" :: "r"(addr), "r"(count)
                 : "memory");
}
__device__ __forceinline__ void mbar_expect_tx(unsigned addr, unsigned bytes) {
    asm volatile("mbarrier.arrive.expect_tx.shared.b64 _, [%0], %1;"
                 :: "r"(addr), "r"(bytes) : "memory");
}
__device__ __forceinline__ void mbar_arrive(unsigned addr) {
    asm volatile("mbarrier.arrive.shared.b64 _, [%0];" :: "r"(addr) : "memory");
}
__device__ __forceinline__ void mbar_wait(unsigned addr, unsigned parity) {
    asm volatile(
        "{\n\t"
        ".reg .pred P1;\n\t"
        "WAIT_LOOP_%=:\n\t"
        "mbarrier.try_wait.parity.shared::cta.b64 P1, [%0], %1;\n\t"
        "@P1 bra.uni WAIT_DONE_%=;\n\t"
        "bra.uni WAIT_LOOP_%=;\n\t"
        "WAIT_DONE_%=:\n\t"
        "}"
        :: "r"(addr), "r"(parity) : "memory");
}
__device__ __forceinline__ void bulk_g2s(unsigned dst_smem, const void* src,
                                         unsigned bytes, unsigned mbar) {
    asm volatile(
        "cp.async.bulk.shared::cluster.global.mbarrier::complete_tx::bytes "
        "[%0], [%1], %2, [%3];"
        :: "r"(dst_smem), "l"(src), "r"(bytes), "r"(mbar) : "memory");
}

// dt arrives as a scalar; reference passes python int 1. Handle either an
// int32 or a float32 payload robustly (deterministic for fixed input).
__device__ __forceinline__ float resolve_dt(const int* dt_raw) {
    int v = __ldg(dt_raw);
    float f = __int_as_float(v);
    float af = fabsf(f);
    if (af >= 1e-6f && af <= 1e6f) return f;
    return (float)v;
}

// ---------------------------------------------------------------------------
// Fast kernel (B=4, H=8, NI=16384).
//   * spikes arrive via TMA bulk loads, 6 chunks (48 t) of lookahead; the
//     only synchronization in the main loop is per-buffer full/empty
//     mbarriers (NO __syncthreads, no staged output, no serialized TMA-out).
//   * f32x2 packs 2 COLUMNS per register; with z0==0 the 4 basis states are
//     shared across heads: 15 issues per 4 outputs.
//   * responses stored directly with STG.64 (64 threads x 8B = 512 B
//     coalesced per (t, head) row).
// CTA = 64 threads = 128 columns x 2 heads. grid = (128, 4) = 512 CTAs.
// ---------------------------------------------------------------------------
__global__ void __launch_bounds__(kBlk)
tb_fast(const float* __restrict__ z0, const float* __restrict__ spikes,
        const float* __restrict__ taus, const float* __restrict__ coeffs,
        const int* __restrict__ dt_raw, float* __restrict__ out, int T)
{
    __shared__ __align__(16) float sspk[kNBuf][kTT][kCols];
    __shared__ __align__(8) unsigned long long fullb[kNBuf], emptyb[kNBuf];

    const int tid  = threadIdx.x;
    const int h0   = blockIdx.y * kHPT;
    const int col0 = blockIdx.x * kCols;
    const int colp = col0 + tid * kCPT;   // this thread's even column

    const float dt = resolve_dt(dt_raw);

    float d[kB];
#pragma unroll
    for (int k = 0; k < kB; ++k)
        d[k] = (float)exp(-(double)dt / (double)__ldg(&taus[k]));

    unsigned long long dd[kB], cc[kHPT][kB];
#pragma unroll
    for (int k = 0; k < kB; ++k) dd[k] = pack2(d[k], d[k]);
#pragma unroll
    for (int hh = 0; hh < kHPT; ++hh)
#pragma unroll
        for (int k = 0; k < kB; ++k) {
            const float c = __ldg(&coeffs[(h0 + hh) * kB + k]);
            cc[hh][k] = pack2(c, c);
        }

    // Initial states: z packed across the column pair, per head.
    unsigned long long z[kHPT][kB];
    bool allz = true;
#pragma unroll
    for (int hh = 0; hh < kHPT; ++hh) {
        const float4 a = *reinterpret_cast<const float4*>(
            z0 + ((size_t)(h0 + hh) * kNI + colp) * kB);
        const float4 b = *reinterpret_cast<const float4*>(
            z0 + ((size_t)(h0 + hh) * kNI + colp + 1) * kB);
        z[hh][0] = pack2(a.x, b.x);
        z[hh][1] = pack2(a.y, b.y);
        z[hh][2] = pack2(a.z, b.z);
        z[hh][3] = pack2(a.w, b.w);
        allz = allz && (a.x==0.f && a.y==0.f && a.z==0.f && a.w==0.f &&
                        b.x==0.f && b.y==0.f && b.z==0.f && b.w==0.f);
    }

    const int nChunks = T / kTT;

    // Barrier init + prologue fills (all by tid 0), one sync total.
    if (tid == 0) {
#pragma unroll
        for (int b = 0; b < kNBuf; ++b) {
            mbar_init(smem_u32(&fullb[b]), 1);
            mbar_init(smem_u32(&emptyb[b]), kBlk);
        }
        asm volatile("fence.proxy.async;" ::: "memory");
#pragma unroll
        for (int b = 0; b < kNBuf; ++b) {
            mbar_expect_tx(smem_u32(&fullb[b]), kSpkChunkB);
#pragma unroll
            for (int j = 0; j < kTT; ++j)
                bulk_g2s(smem_u32(&sspk[b][j][0]),
                         spikes + (size_t)(b * kTT + j) * kNI + col0,
                         kSpkRowB, smem_u32(&fullb[b]));
        }
    }
    __syncthreads();

    float* ob = out + (size_t)h0 * kNI + colp;   // head h0, t = 0
    constexpr long long OH = (long long)kNI;     // head stride (floats)
    constexpr long long OT = (long long)kH * kNI;

    for (int c = 0; c < nChunks; ++c) {
        const int buf = c % kNBuf;
        const unsigned par = (unsigned)((c / kNBuf) & 1);

        mbar_wait(smem_u32(&fullb[buf]), par);

        if (allz) {
            // States shared across heads (z0 == 0).
#pragma unroll
            for (int j = 0; j < kTT; ++j) {
                const float2 s =
                    reinterpret_cast<const float2*>(sspk[buf][j])[tid];
                const unsigned long long ss = pack2(s.x, s.y);
#pragma unroll
                for (int k = 0; k < kB; ++k)
                    z[0][k] = fma2(dd[k], z[0][k], ss);
#pragma unroll
                for (int hh = 0; hh < kHPT; ++hh) {
                    unsigned long long r = mul2(cc[hh][0], z[0][0]);
                    r = fma2(cc[hh][1], z[0][1], r);
                    r = fma2(cc[hh][2], z[0][2], r);
                    r = fma2(cc[hh][3], z[0][3], r);
                    float lo, hi;
                    unpack2(r, lo, hi);
                    *reinterpret_cast<float2*>(ob + (size_t)j * OT +
                                               (size_t)hh * OH) =
                        make_float2(lo, hi);
                }
            }
        } else {
#pragma unroll
            for (int j = 0; j < kTT; ++j) {
                const float2 s =
                    reinterpret_cast<const float2*>(sspk[buf][j])[tid];
                const unsigned long long ss = pack2(s.x, s.y);
#pragma unroll
                for (int hh = 0; hh < kHPT; ++hh) {
#pragma unroll
                    for (int k = 0; k < kB; ++k)
                        z[hh][k] = fma2(dd[k], z[hh][k], ss);
                    unsigned long long r = mul2(cc[hh][0], z[hh][0]);
                    r = fma2(cc[hh][1], z[hh][1], r);
                    r = fma2(cc[hh][2], z[hh][2], r);
                    r = fma2(cc[hh][3], z[hh][3], r);
                    float lo, hi;
                    unpack2(r, lo, hi);
                    *reinterpret_cast<float2*>(ob + (size_t)j * OT +
                                               (size_t)hh * OH) =
                        make_float2(lo, hi);
                }
            }
        }
        ob += (size_t)kTT * OT;

        // Signal buffer consumed; producer refills with 5 chunks of slack.
        mbar_arrive(smem_u32(&emptyb[buf]));
        if (tid == 0) {
            const int cn = c + kNBuf;
            if (cn < nChunks) {
                mbar_wait(smem_u32(&emptyb[buf]), par);
                mbar_expect_tx(smem_u32(&fullb[buf]), kSpkChunkB);
#pragma unroll
                for (int j = 0; j < kTT; ++j)
                    bulk_g2s(smem_u32(&sspk[buf][j][0]),
                             spikes + (size_t)(cn * kTT + j) * kNI + col0,
                             kSpkRowB, smem_u32(&fullb[buf]));
            }
        }
    }
}

// ---------------------------------------------------------------------------
// Generic fallback (any shapes, Bn <= 16): one thread per (head, idx).
// ---------------------------------------------------------------------------
__global__ void tb_generic(const float* __restrict__ z0,
                           const float* __restrict__ spikes,
                           const float* __restrict__ taus,
                           const float* __restrict__ coeffs,
                           const int* __restrict__ dt_raw,
                           float* __restrict__ out,
                           int T, int NI, int Hn, int Bn)
{
    const int gid = blockIdx.x * blockDim.x + threadIdx.x;
    if (gid >= NI * Hn) return;
    const int idx = gid % NI;
    const int h   = gid / NI;

    const float dt = resolve_dt(dt_raw);

    constexpr int BMAX = 16;
    float z[BMAX], dk[BMAX], ck[BMAX];
    const int Bc = Bn < BMAX ? Bn : BMAX;
    for (int k = 0; k < Bc; ++k) {
        dk[k] = (float)exp(-(double)dt / (double)taus[k]);
        ck[k] = coeffs[h * Bn + k];
        z[k]  = z0[((size_t)h * NI + idx) * Bn + k];
    }
    const float* sp = spikes + idx;
    float* op = out + (size_t)h * NI + idx;
    for (int t = 0; t < T; ++t) {
        const float s = sp[(size_t)t * NI];
        float r = 0.0f;
        for (int k = 0; k < Bc; ++k) {
            z[k] = fmaf(dk[k], z[k], s);
            r = fmaf(ck[k], z[k], r);
        }
        op[(size_t)t * Hn * NI] = r;
    }
}

}  // namespace

extern "C" void kernel_launch(void* const* d_in, const int* in_sizes, int n_in,
                              void* d_out, int out_size)
{
    const float* z0     = (const float*)d_in[0];
    const float* spikes = (const float*)d_in[1];
    const float* taus   = (const float*)d_in[2];
    const float* coeffs = (const float*)d_in[3];

    const int* dt_ptr;
    if (n_in >= 5) {
        dt_ptr = (const int*)d_in[4];
    } else {
        static int* p = nullptr;
        if (!p) cudaGetSymbolAddress((void**)&p, g_dt_default);
        dt_ptr = p;
    }

    float* out = (float*)d_out;

    const int Bn = in_sizes[2];
    const int Hn = in_sizes[3] / Bn;
    const int NI = in_sizes[0] / (Hn * Bn);
    const int T  = in_sizes[1] / NI;

    if (Bn == kB && Hn == kH && NI == kNI && (T % kTT) == 0 &&
        T >= kTT * kNBuf) {
        dim3 grid(kNI / kCols, kH / kHPT);
        tb_fast<<<grid, kBlk>>>(z0, spikes, taus, coeffs, dt_ptr, out, T);
    } else {
        const int threads = NI * Hn;
        tb_generic<<<(threads + 127) / 128, 128>>>(
            z0, spikes, taus, coeffs, dt_ptr, out, T, NI, Hn, Bn);
    }
}